// round 1
// baseline (speedup 1.0000x reference)
#include <cuda_runtime.h>
#include <cstdint>

#define NN 50000        // nodes
#define NE 800000       // edges
#define NG 64           // graphs
#define DD 96           // dim
#define NL 4            // GIN layers
#define NH 5            // heads
#define BN_EPS 1e-5f

// ---------------- scratch (static device globals; no allocs allowed) ----------
__device__ __align__(256) float g_h  [NN * DD];
__device__ __align__(256) float g_agg[NN * DD];   // also reused as z2 output
__device__ __align__(256) float g_y  [NN * DD];
__device__ __align__(256) float g_stats[NL * 2 * 2 * DD];  // [layer][stage][{sum,sumsq}][D]
__device__ __align__(256) float g_aff[2 * DD];             // current {s, t}
__device__ __align__(256) unsigned g_pool[NH * NG * DD];   // order-preserving keys

// ---------------- init: zero stats + pool keys ------------------------------
__global__ void init_kernel() {
    int idx = blockIdx.x * blockDim.x + threadIdx.x;
    int nstats = NL * 2 * 2 * DD;
    int npool  = NH * NG * DD;
    for (int i = idx; i < nstats; i += gridDim.x * blockDim.x) g_stats[i] = 0.f;
    for (int i = idx; i < npool;  i += gridDim.x * blockDim.x) g_pool[i] = 0u; // key of -NaN: below everything
}

// ---------------- zero agg ---------------------------------------------------
__global__ void zero_agg_kernel() {
    int idx = blockIdx.x * blockDim.x + threadIdx.x;
    float4* a4 = reinterpret_cast<float4*>(g_agg);
    if (idx < NN * (DD / 4)) a4[idx] = make_float4(0.f, 0.f, 0.f, 0.f);
}

// ---------------- edge scatter: agg[dst] += h[src]  (vector RED) -------------
__global__ __launch_bounds__(256) void scatter_kernel(
    const float4* __restrict__ h4,
    const int* __restrict__ src,
    const int* __restrict__ dst)
{
    int idx = blockIdx.x * blockDim.x + threadIdx.x;
    const int total = NE * (DD / 4);
    if (idx >= total) return;
    int e = idx / (DD / 4);
    int c = idx - e * (DD / 4);
    int s = __ldg(&src[e]);
    int d = __ldg(&dst[e]);
    float4 v = __ldg(&h4[s * (DD / 4) + c]);
    float* p = reinterpret_cast<float*>(
        const_cast<float4*>(reinterpret_cast<const float4*>(g_agg)) + d * (DD / 4) + c);
    asm volatile("red.global.add.v4.f32 [%0], {%1, %2, %3, %4};"
                 :: "l"(p), "f"(v.x), "f"(v.y), "f"(v.z), "f"(v.w) : "memory");
}

// ---------------- fused GEMM (+optional affine/relu prologue, +stats) --------
// out[r][c] = (prologue(A[r]))[k] dot W[k][c] + bias[c]; stats += colsum/colsumsq
// MODE 0: z = A + B          (GIN input: h + agg)
// MODE 1: z = relu(s*A + t)  (BN1 + ReLU folded into load)
template<int MODE>
__global__ __launch_bounds__(128) void gemm_kernel(
    const float* __restrict__ A, const float* __restrict__ B,
    const float* __restrict__ W, const float* __restrict__ bias,
    const float* __restrict__ aff,
    float* __restrict__ out, float* __restrict__ stats)
{
    constexpr int TR = 64;      // rows per block
    constexpr int SROW = 100;   // smem row stride (floats): bank-staggered, 16B-aligned
    extern __shared__ float sm[];
    float* zs = sm;             // TR * SROW
    float* ws = sm + TR * SROW; // 96*96

    const int tid = threadIdx.x;
    const int tx = tid & 15;    // col group
    const int ty = tid >> 4;    // row group
    const int row0 = blockIdx.x * TR;

    // load W tile (96x96)
    {
        float4* ws4 = reinterpret_cast<float4*>(ws);
        const float4* W4 = reinterpret_cast<const float4*>(W);
        #pragma unroll
        for (int i = 0; i < (DD * DD / 4) / 128; i++)
            ws4[tid + i * 128] = W4[tid + i * 128];
    }
    // load z tile (64 rows x 96), apply prologue
    #pragma unroll
    for (int t = 0; t < (TR * (DD / 4)) / 128; t++) {
        int i = tid + t * 128;
        int r = i / (DD / 4), c4 = i - r * (DD / 4);
        int grow = row0 + r;
        float4 v;
        if (grow < NN) {
            v = reinterpret_cast<const float4*>(A)[grow * (DD / 4) + c4];
            if (MODE == 0) {
                float4 b = reinterpret_cast<const float4*>(B)[grow * (DD / 4) + c4];
                v.x += b.x; v.y += b.y; v.z += b.z; v.w += b.w;
            } else {
                int k = c4 * 4;
                v.x = fmaxf(aff[k + 0] * v.x + aff[DD + k + 0], 0.f);
                v.y = fmaxf(aff[k + 1] * v.y + aff[DD + k + 1], 0.f);
                v.z = fmaxf(aff[k + 2] * v.z + aff[DD + k + 2], 0.f);
                v.w = fmaxf(aff[k + 3] * v.w + aff[DD + k + 3], 0.f);
            }
        } else {
            v = make_float4(0.f, 0.f, 0.f, 0.f);
        }
        *reinterpret_cast<float4*>(zs + r * SROW + c4 * 4) = v;
    }
    __syncthreads();

    // register-blocked compute: 8 rows (r = i*8 + ty) x 6 cols (c = tx + 16*j)
    float acc[8][6];
    #pragma unroll
    for (int i = 0; i < 8; i++)
        #pragma unroll
        for (int j = 0; j < 6; j++) acc[i][j] = 0.f;

    #pragma unroll 4
    for (int k = 0; k < DD; k++) {
        float a[8], w[6];
        #pragma unroll
        for (int i = 0; i < 8; i++) a[i] = zs[(i * 8 + ty) * SROW + k];
        #pragma unroll
        for (int j = 0; j < 6; j++) w[j] = ws[k * DD + tx + 16 * j];
        #pragma unroll
        for (int i = 0; i < 8; i++)
            #pragma unroll
            for (int j = 0; j < 6; j++) acc[i][j] = fmaf(a[i], w[j], acc[i][j]);
    }

    // epilogue: +bias, store, per-thread column stats
    float bv[6];
    #pragma unroll
    for (int j = 0; j < 6; j++) bv[j] = __ldg(&bias[tx + 16 * j]);
    float cs[6], cq[6];
    #pragma unroll
    for (int j = 0; j < 6; j++) { cs[j] = 0.f; cq[j] = 0.f; }

    #pragma unroll
    for (int i = 0; i < 8; i++) {
        int grow = row0 + i * 8 + ty;
        if (grow < NN) {
            #pragma unroll
            for (int j = 0; j < 6; j++) {
                float v = acc[i][j] + bv[j];
                out[grow * DD + tx + 16 * j] = v;
                cs[j] += v;
                cq[j] += v * v;
            }
        }
    }

    __syncthreads();  // done reading zs/ws; reuse smem for reduction
    float* sred = sm; // [2][8][96]
    #pragma unroll
    for (int j = 0; j < 6; j++) {
        int c = tx + 16 * j;
        sred[ty * DD + c] = cs[j];
        sred[8 * DD + ty * DD + c] = cq[j];
    }
    __syncthreads();
    if (tid < DD) {
        float s = 0.f, q = 0.f;
        #pragma unroll
        for (int t = 0; t < 8; t++) {
            s += sred[t * DD + tid];
            q += sred[8 * DD + t * DD + tid];
        }
        atomicAdd(&stats[tid], s);
        atomicAdd(&stats[DD + tid], q);
    }
}

// ---------------- stats -> affine (s,t) --------------------------------------
__global__ void finalize_kernel(const float* __restrict__ stats,
                                const float* __restrict__ gamma,
                                const float* __restrict__ beta)
{
    int c = threadIdx.x;
    if (c >= DD) return;
    const float inv_n = 1.f / (float)NN;
    float mean = stats[c] * inv_n;
    float var  = stats[DD + c] * inv_n - mean * mean;
    float s = gamma[c] * rsqrtf(var + BN_EPS);
    g_aff[c] = s;
    g_aff[DD + c] = beta[c] - mean * s;
}

// ---------------- prelu(affine(z2)) -> h -------------------------------------
__global__ __launch_bounds__(256) void prelu_kernel(const float* __restrict__ prelu_a) {
    int idx = blockIdx.x * blockDim.x + threadIdx.x;
    if (idx >= NN * (DD / 4)) return;
    int c4 = idx % (DD / 4);
    int k = c4 * 4;
    float a = __ldg(prelu_a);
    float4 v = reinterpret_cast<const float4*>(g_agg)[idx];  // z2 lives in g_agg
    float u;
    u = g_aff[k + 0] * v.x + g_aff[DD + k + 0]; v.x = (u >= 0.f) ? u : a * u;
    u = g_aff[k + 1] * v.y + g_aff[DD + k + 1]; v.y = (u >= 0.f) ? u : a * u;
    u = g_aff[k + 2] * v.z + g_aff[DD + k + 2]; v.z = (u >= 0.f) ? u : a * u;
    u = g_aff[k + 3] * v.w + g_aff[DD + k + 3]; v.w = (u >= 0.f) ? u : a * u;
    reinterpret_cast<float4*>(g_h)[idx] = v;
}

// ---------------- per-graph max pool (graphs are contiguous row ranges) ------
__device__ __forceinline__ unsigned f2key(float f) {
    int i = __float_as_int(f);
    return (i >= 0) ? ((unsigned)i ^ 0x80000000u) : ~(unsigned)i;
}
__global__ void pool_kernel(const float* __restrict__ h, int slot) {
    int g = blockIdx.x, part = blockIdx.y, d = threadIdx.x;
    int lo_g = (g * NN + (NG - 1)) / NG;
    int hi_g = ((g + 1) * NN + (NG - 1)) / NG;
    int chunk = (hi_g - lo_g + 7) >> 3;
    int lo = lo_g + part * chunk;
    int hi = min(hi_g, lo + chunk);
    float m = -3.402823466e38f;
    for (int r = lo; r < hi; r++) m = fmaxf(m, __ldg(&h[r * DD + d]));
    if (hi > lo) atomicMax(&g_pool[slot * NG * DD + g * DD + d], f2key(m));
}

// ---------------- heads: out[g, d*5+l] = pool[l][g] @ linW[l] + linb[l] ------
__global__ void heads_kernel(const float* __restrict__ lin_W,
                             const float* __restrict__ lin_b,
                             float* __restrict__ out)
{
    extern __shared__ float sm[];
    float* ps = sm;             // 64*96
    float* ws = sm + NG * DD;   // 96*96
    int l = blockIdx.x, tid = threadIdx.x;

    for (int i = tid; i < NG * DD; i += DD) {
        unsigned key = g_pool[l * NG * DD + i];
        int b = (key & 0x80000000u) ? (int)(key ^ 0x80000000u) : (int)(~key);
        ps[i] = __int_as_float(b);
    }
    for (int i = tid; i < DD * DD; i += DD) ws[i] = lin_W[l * DD * DD + i];
    __syncthreads();

    float bv = lin_b[l * DD + tid];
    for (int g = 0; g < NG; g++) {
        float acc = bv;
        #pragma unroll 4
        for (int k = 0; k < DD; k++) acc = fmaf(ps[g * DD + k], ws[k * DD + tid], acc);
        out[g * (DD * NH) + tid * NH + l] = acc;
    }
}

// ---------------- host orchestration -----------------------------------------
extern "C" void kernel_launch(void* const* d_in, const int* in_sizes, int n_in,
                              void* d_out, int out_size)
{
    const float* h_in   = (const float*)d_in[0];
    const float* W1     = (const float*)d_in[1];
    const float* b1     = (const float*)d_in[2];
    const float* bn1g   = (const float*)d_in[3];
    const float* bn1b   = (const float*)d_in[4];
    const float* W2     = (const float*)d_in[5];
    const float* b2     = (const float*)d_in[6];
    const float* bng    = (const float*)d_in[7];
    const float* bnb    = (const float*)d_in[8];
    const float* prelua = (const float*)d_in[9];
    const float* linW   = (const float*)d_in[10];
    const float* linb   = (const float*)d_in[11];
    const int*   src    = (const int*)d_in[12];
    const int*   dst    = (const int*)d_in[13];
    float* out = (float*)d_out;

    void* p;
    cudaGetSymbolAddress(&p, g_h);     float* hbuf = (float*)p;
    cudaGetSymbolAddress(&p, g_agg);   float* abuf = (float*)p;
    cudaGetSymbolAddress(&p, g_y);     float* ybuf = (float*)p;
    cudaGetSymbolAddress(&p, g_stats); float* stats = (float*)p;
    cudaGetSymbolAddress(&p, g_aff);   float* aff = (float*)p;

    const int gemm_smem  = (64 * 100 + DD * DD) * (int)sizeof(float);   // 62464 B
    const int heads_smem = (NG * DD + DD * DD) * (int)sizeof(float);    // 61440 B
    cudaFuncSetAttribute(gemm_kernel<0>, cudaFuncAttributeMaxDynamicSharedMemorySize, gemm_smem);
    cudaFuncSetAttribute(gemm_kernel<1>, cudaFuncAttributeMaxDynamicSharedMemorySize, gemm_smem);
    cudaFuncSetAttribute(heads_kernel,   cudaFuncAttributeMaxDynamicSharedMemorySize, heads_smem);

    const int gemm_blocks = (NN + 63) / 64;                 // 782
    const int scat_threads = NE * (DD / 4);                 // 19.2M
    const int scat_blocks = (scat_threads + 255) / 256;
    const int elt_blocks = (NN * (DD / 4) + 255) / 256;

    init_kernel<<<128, 256>>>();
    pool_kernel<<<dim3(NG, 8), DD>>>(h_in, 0);

    for (int l = 0; l < NL; l++) {
        const float* hcur = (l == 0) ? h_in : hbuf;
        float* st1 = stats + (l * 2 + 0) * 2 * DD;
        float* st2 = stats + (l * 2 + 1) * 2 * DD;

        zero_agg_kernel<<<elt_blocks, 256>>>();
        scatter_kernel<<<scat_blocks, 256>>>(
            reinterpret_cast<const float4*>(hcur), src, dst);

        // y = (h + agg) @ W1 + b1 ; collect stats1
        gemm_kernel<0><<<gemm_blocks, 128, gemm_smem>>>(
            hcur, abuf, W1 + l * DD * DD, b1 + l * DD, aff, ybuf, st1);
        finalize_kernel<<<1, DD>>>(st1, bn1g + l * DD, bn1b + l * DD);

        // z2 = relu(bn1(y)) @ W2 + b2 ; collect stats2 ; z2 -> g_agg
        gemm_kernel<1><<<gemm_blocks, 128, gemm_smem>>>(
            ybuf, nullptr, W2 + l * DD * DD, b2 + l * DD, aff, abuf, st2);
        finalize_kernel<<<1, DD>>>(st2, bng + l * DD, bnb + l * DD);

        // h = prelu(bn(z2))
        prelu_kernel<<<elt_blocks, 256>>>(prelua);
        pool_kernel<<<dim3(NG, 8), DD>>>(hbuf, l + 1);
    }

    heads_kernel<<<NH, DD, heads_smem>>>(linW, linb, out);
}

// round 2
// speedup vs baseline: 1.4855x; 1.4855x over previous
#include <cuda_runtime.h>
#include <cstdint>

#define NN 50000        // nodes
#define NE 800000       // edges
#define NG 64           // graphs
#define DD 96           // dim
#define NL 4            // GIN layers
#define NH 5            // heads
#define BN_EPS 1e-5f
#define SCAN_BLK 196    // ceil(50000/256)

// ---------------- scratch (static device globals; no allocs allowed) ----------
__device__ __align__(256) float g_h  [NN * DD];
__device__ __align__(256) float g_agg[NN * DD];   // z buffer (h+agg), then z2
__device__ __align__(256) float g_y  [NN * DD];
__device__ __align__(256) float g_stats[NL * 2 * 2 * DD];
__device__ __align__(256) float g_aff[2 * DD];
__device__ __align__(256) unsigned g_pool[NH * NG * DD];
// CSR scratch
__device__ __align__(256) int g_cnt [NN];
__device__ __align__(256) int g_off [NN + 1];
__device__ __align__(256) int g_eidx[NE];
__device__ __align__(256) int g_bsum[256];

// ---------------- init: zero stats + pool keys + degree counters --------------
__global__ void init_kernel() {
    int idx = blockIdx.x * blockDim.x + threadIdx.x;
    int stride = gridDim.x * blockDim.x;
    for (int i = idx; i < NL * 2 * 2 * DD; i += stride) g_stats[i] = 0.f;
    for (int i = idx; i < NH * NG * DD; i += stride) g_pool[i] = 0u;
    for (int i = idx; i < NN; i += stride) g_cnt[i] = 0;
}

// ---------------- CSR build ---------------------------------------------------
__global__ void csr_count_kernel(const int* __restrict__ dst) {
    int e = blockIdx.x * blockDim.x + threadIdx.x;
    if (e < NE) atomicAdd(&g_cnt[dst[e]], 1);
}

__global__ void scanA_kernel() {
    __shared__ int s[256];
    int t = threadIdx.x;
    int idx = blockIdx.x * 256 + t;
    int c = (idx < NN) ? g_cnt[idx] : 0;
    s[t] = c; __syncthreads();
    #pragma unroll
    for (int o = 128; o > 0; o >>= 1) {
        if (t < o) s[t] += s[t + o];
        __syncthreads();
    }
    if (t == 0) g_bsum[blockIdx.x] = s[0];
}

__global__ void scanB_kernel() {
    __shared__ int s[256];
    int t = threadIdx.x;
    int v = (t < SCAN_BLK) ? g_bsum[t] : 0;
    s[t] = v; __syncthreads();
    #pragma unroll
    for (int o = 1; o < 256; o <<= 1) {
        int x = (t >= o) ? s[t - o] : 0;
        __syncthreads();
        s[t] += x;
        __syncthreads();
    }
    g_bsum[t] = s[t] - v;   // exclusive
}

__global__ void scanC_kernel() {
    __shared__ int s[256];
    int t = threadIdx.x;
    int idx = blockIdx.x * 256 + t;
    int c = (idx < NN) ? g_cnt[idx] : 0;
    s[t] = c; __syncthreads();
    #pragma unroll
    for (int o = 1; o < 256; o <<= 1) {
        int x = (t >= o) ? s[t - o] : 0;
        __syncthreads();
        s[t] += x;
        __syncthreads();
    }
    int excl = g_bsum[blockIdx.x] + s[t] - c;
    if (idx < NN) { g_off[idx] = excl; g_cnt[idx] = 0; }
    if (idx == NN - 1) g_off[NN] = excl + c;
}

__global__ void csr_fill_kernel(const int* __restrict__ src,
                                const int* __restrict__ dst) {
    int e = blockIdx.x * blockDim.x + threadIdx.x;
    if (e >= NE) return;
    int d = dst[e];
    int pos = g_off[d] + atomicAdd(&g_cnt[d], 1);
    g_eidx[pos] = src[e];
}

// ---------------- gather aggregation: z[i] = h[i] + sum_{j in N(i)} h[j] ------
__global__ __launch_bounds__(256) void agg_kernel(const float4* __restrict__ h4,
                                                  float4* __restrict__ z4) {
    int gtid = blockIdx.x * 256 + threadIdx.x;
    int node = gtid >> 5;
    int lane = threadIdx.x & 31;
    if (node >= NN || lane >= 24) return;
    int o0 = g_off[node], o1 = g_off[node + 1];
    float4 acc = __ldg(&h4[node * 24 + lane]);
    float4 acc2 = make_float4(0.f, 0.f, 0.f, 0.f);
    int j = o0;
    for (; j + 1 < o1; j += 2) {
        int s0 = __ldg(&g_eidx[j]);
        int s1 = __ldg(&g_eidx[j + 1]);
        float4 v0 = __ldg(&h4[s0 * 24 + lane]);
        float4 v1 = __ldg(&h4[s1 * 24 + lane]);
        acc.x += v0.x; acc.y += v0.y; acc.z += v0.z; acc.w += v0.w;
        acc2.x += v1.x; acc2.y += v1.y; acc2.z += v1.z; acc2.w += v1.w;
    }
    if (j < o1) {
        int s0 = __ldg(&g_eidx[j]);
        float4 v0 = __ldg(&h4[s0 * 24 + lane]);
        acc.x += v0.x; acc.y += v0.y; acc.z += v0.z; acc.w += v0.w;
    }
    acc.x += acc2.x; acc.y += acc2.y; acc.z += acc2.z; acc.w += acc2.w;
    z4[node * 24 + lane] = acc;
}

// ---------------- packed f32x2 helpers ----------------------------------------
__device__ __forceinline__ unsigned long long pk2(float x) {
    unsigned long long r;
    asm("mov.b64 %0, {%1, %1};" : "=l"(r) : "f"(x));
    return r;
}
__device__ __forceinline__ void fma2(unsigned long long& d,
                                     unsigned long long a, unsigned long long b) {
    asm("fma.rn.f32x2 %0, %1, %2, %0;" : "+l"(d) : "l"(a), "l"(b));
}
__device__ __forceinline__ void unpk2(unsigned long long v, float& lo, float& hi) {
    asm("mov.b64 {%0, %1}, %2;" : "=f"(lo), "=f"(hi) : "l"(v));
}

// ---------------- fused GEMM (+optional affine/relu prologue, +stats) ---------
// MODE 0: z = A                (aggregation already produced h+agg)
// MODE 1: z = relu(s*A + t)    (BN1 + ReLU folded into load)
template<int MODE>
__global__ __launch_bounds__(128) void gemm_kernel(
    const float* __restrict__ A,
    const float* __restrict__ W, const float* __restrict__ bias,
    const float* __restrict__ aff,
    float* __restrict__ out, float* __restrict__ stats)
{
    constexpr int TR = 64;
    constexpr int SROW = 100;
    extern __shared__ float sm[];
    float* zs = sm;               // TR * SROW
    float* ws = sm + TR * SROW;   // 96*96

    const int tid = threadIdx.x;
    const int tx = tid & 15;
    const int ty = tid >> 4;
    const int row0 = blockIdx.x * TR;

    {
        float4* ws4 = reinterpret_cast<float4*>(ws);
        const float4* W4 = reinterpret_cast<const float4*>(W);
        #pragma unroll
        for (int i = 0; i < (DD * DD / 4) / 128; i++)
            ws4[tid + i * 128] = W4[tid + i * 128];
    }
    #pragma unroll
    for (int t = 0; t < (TR * (DD / 4)) / 128; t++) {
        int i = tid + t * 128;
        int r = i / (DD / 4), c4 = i - r * (DD / 4);
        int grow = row0 + r;
        float4 v;
        if (grow < NN) {
            v = reinterpret_cast<const float4*>(A)[grow * (DD / 4) + c4];
            if (MODE == 1) {
                int k = c4 * 4;
                v.x = fmaxf(aff[k + 0] * v.x + aff[DD + k + 0], 0.f);
                v.y = fmaxf(aff[k + 1] * v.y + aff[DD + k + 1], 0.f);
                v.z = fmaxf(aff[k + 2] * v.z + aff[DD + k + 2], 0.f);
                v.w = fmaxf(aff[k + 3] * v.w + aff[DD + k + 3], 0.f);
            }
        } else {
            v = make_float4(0.f, 0.f, 0.f, 0.f);
        }
        *reinterpret_cast<float4*>(zs + r * SROW + c4 * 4) = v;
    }
    __syncthreads();

    // 8 rows (r = 8i+ty) x 3 column-pairs (c = 2tx + 32j, +1), packed f32x2
    unsigned long long acc[8][3];
    #pragma unroll
    for (int i = 0; i < 8; i++)
        #pragma unroll
        for (int j = 0; j < 3; j++) acc[i][j] = 0ull;

    const int cbase = 2 * tx;
    #pragma unroll 8
    for (int k = 0; k < DD; k++) {
        unsigned long long a2[8], w2[3];
        #pragma unroll
        for (int i = 0; i < 8; i++) a2[i] = pk2(zs[(8 * i + ty) * SROW + k]);
        #pragma unroll
        for (int j = 0; j < 3; j++)
            w2[j] = *reinterpret_cast<const unsigned long long*>(ws + k * DD + cbase + 32 * j);
        #pragma unroll
        for (int i = 0; i < 8; i++)
            #pragma unroll
            for (int j = 0; j < 3; j++) fma2(acc[i][j], a2[i], w2[j]);
    }

    // epilogue: +bias, store float2, per-thread column stats
    float blo[3], bhi[3];
    #pragma unroll
    for (int j = 0; j < 3; j++) {
        blo[j] = __ldg(&bias[cbase + 32 * j]);
        bhi[j] = __ldg(&bias[cbase + 32 * j + 1]);
    }
    float cs[6], cq[6];
    #pragma unroll
    for (int j = 0; j < 6; j++) { cs[j] = 0.f; cq[j] = 0.f; }

    #pragma unroll
    for (int i = 0; i < 8; i++) {
        int grow = row0 + 8 * i + ty;
        if (grow < NN) {
            #pragma unroll
            for (int j = 0; j < 3; j++) {
                float lo, hi;
                unpk2(acc[i][j], lo, hi);
                lo += blo[j]; hi += bhi[j];
                *reinterpret_cast<float2*>(out + grow * DD + cbase + 32 * j) =
                    make_float2(lo, hi);
                cs[2 * j] += lo;     cq[2 * j] += lo * lo;
                cs[2 * j + 1] += hi; cq[2 * j + 1] += hi * hi;
            }
        }
    }

    __syncthreads();
    float* sred = sm; // [2][8][96]
    #pragma unroll
    for (int j = 0; j < 3; j++) {
        #pragma unroll
        for (int q = 0; q < 2; q++) {
            int c = cbase + 32 * j + q;
            sred[ty * DD + c] = cs[2 * j + q];
            sred[8 * DD + ty * DD + c] = cq[2 * j + q];
        }
    }
    __syncthreads();
    if (tid < DD) {
        float s = 0.f, q = 0.f;
        #pragma unroll
        for (int t = 0; t < 8; t++) {
            s += sred[t * DD + tid];
            q += sred[8 * DD + t * DD + tid];
        }
        atomicAdd(&stats[tid], s);
        atomicAdd(&stats[DD + tid], q);
    }
}

// ---------------- stats -> affine (s,t) --------------------------------------
__global__ void finalize_kernel(const float* __restrict__ stats,
                                const float* __restrict__ gamma,
                                const float* __restrict__ beta)
{
    int c = threadIdx.x;
    if (c >= DD) return;
    const float inv_n = 1.f / (float)NN;
    float mean = stats[c] * inv_n;
    float var  = stats[DD + c] * inv_n - mean * mean;
    float s = gamma[c] * rsqrtf(var + BN_EPS);
    g_aff[c] = s;
    g_aff[DD + c] = beta[c] - mean * s;
}

// ---------------- prelu(affine(z2)) -> h -------------------------------------
__global__ __launch_bounds__(256) void prelu_kernel(const float* __restrict__ prelu_a) {
    int idx = blockIdx.x * blockDim.x + threadIdx.x;
    if (idx >= NN * (DD / 4)) return;
    int c4 = idx % (DD / 4);
    int k = c4 * 4;
    float a = __ldg(prelu_a);
    float4 v = reinterpret_cast<const float4*>(g_agg)[idx];
    float u;
    u = g_aff[k + 0] * v.x + g_aff[DD + k + 0]; v.x = (u >= 0.f) ? u : a * u;
    u = g_aff[k + 1] * v.y + g_aff[DD + k + 1]; v.y = (u >= 0.f) ? u : a * u;
    u = g_aff[k + 2] * v.z + g_aff[DD + k + 2]; v.z = (u >= 0.f) ? u : a * u;
    u = g_aff[k + 3] * v.w + g_aff[DD + k + 3]; v.w = (u >= 0.f) ? u : a * u;
    reinterpret_cast<float4*>(g_h)[idx] = v;
}

// ---------------- per-graph max pool -----------------------------------------
__device__ __forceinline__ unsigned f2key(float f) {
    int i = __float_as_int(f);
    return (i >= 0) ? ((unsigned)i ^ 0x80000000u) : ~(unsigned)i;
}
__global__ void pool_kernel(const float* __restrict__ h, int slot) {
    int g = blockIdx.x, part = blockIdx.y, d = threadIdx.x;
    int lo_g = (g * NN + (NG - 1)) / NG;
    int hi_g = ((g + 1) * NN + (NG - 1)) / NG;
    int chunk = (hi_g - lo_g + 7) >> 3;
    int lo = lo_g + part * chunk;
    int hi = min(hi_g, lo + chunk);
    float m = -3.402823466e38f;
    for (int r = lo; r < hi; r++) m = fmaxf(m, __ldg(&h[r * DD + d]));
    if (hi > lo) atomicMax(&g_pool[slot * NG * DD + g * DD + d], f2key(m));
}

// ---------------- heads ------------------------------------------------------
__global__ void heads_kernel(const float* __restrict__ lin_W,
                             const float* __restrict__ lin_b,
                             float* __restrict__ out)
{
    extern __shared__ float sm[];
    float* ps = sm;
    float* ws = sm + NG * DD;
    int l = blockIdx.x, tid = threadIdx.x;

    for (int i = tid; i < NG * DD; i += DD) {
        unsigned key = g_pool[l * NG * DD + i];
        int b = (key & 0x80000000u) ? (int)(key ^ 0x80000000u) : (int)(~key);
        ps[i] = __int_as_float(b);
    }
    for (int i = tid; i < DD * DD; i += DD) ws[i] = lin_W[l * DD * DD + i];
    __syncthreads();

    float bv = lin_b[l * DD + tid];
    for (int g = 0; g < NG; g++) {
        float acc = bv;
        #pragma unroll 4
        for (int k = 0; k < DD; k++) acc = fmaf(ps[g * DD + k], ws[k * DD + tid], acc);
        out[g * (DD * NH) + tid * NH + l] = acc;
    }
}

// ---------------- host orchestration -----------------------------------------
extern "C" void kernel_launch(void* const* d_in, const int* in_sizes, int n_in,
                              void* d_out, int out_size)
{
    const float* h_in   = (const float*)d_in[0];
    const float* W1     = (const float*)d_in[1];
    const float* b1     = (const float*)d_in[2];
    const float* bn1g   = (const float*)d_in[3];
    const float* bn1b   = (const float*)d_in[4];
    const float* W2     = (const float*)d_in[5];
    const float* b2     = (const float*)d_in[6];
    const float* bng    = (const float*)d_in[7];
    const float* bnb    = (const float*)d_in[8];
    const float* prelua = (const float*)d_in[9];
    const float* linW   = (const float*)d_in[10];
    const float* linb   = (const float*)d_in[11];
    const int*   src    = (const int*)d_in[12];
    const int*   dst    = (const int*)d_in[13];
    float* out = (float*)d_out;

    void* p;
    cudaGetSymbolAddress(&p, g_h);     float* hbuf = (float*)p;
    cudaGetSymbolAddress(&p, g_agg);   float* zbuf = (float*)p;
    cudaGetSymbolAddress(&p, g_y);     float* ybuf = (float*)p;
    cudaGetSymbolAddress(&p, g_stats); float* stats = (float*)p;
    cudaGetSymbolAddress(&p, g_aff);   float* aff = (float*)p;

    const int gemm_smem  = (64 * 100 + DD * DD) * (int)sizeof(float);
    const int heads_smem = (NG * DD + DD * DD) * (int)sizeof(float);
    cudaFuncSetAttribute(gemm_kernel<0>, cudaFuncAttributeMaxDynamicSharedMemorySize, gemm_smem);
    cudaFuncSetAttribute(gemm_kernel<1>, cudaFuncAttributeMaxDynamicSharedMemorySize, gemm_smem);
    cudaFuncSetAttribute(heads_kernel,   cudaFuncAttributeMaxDynamicSharedMemorySize, heads_smem);

    const int gemm_blocks = (NN + 63) / 64;
    const int edge_blocks = (NE + 255) / 256;
    const int elt_blocks  = (NN * (DD / 4) + 255) / 256;
    const int agg_blocks  = (NN * 32 + 255) / 256;

    // init + CSR build (once per launch, reused by all 4 layers)
    init_kernel<<<128, 256>>>();
    csr_count_kernel<<<edge_blocks, 256>>>(dst);
    scanA_kernel<<<SCAN_BLK, 256>>>();
    scanB_kernel<<<1, 256>>>();
    scanC_kernel<<<SCAN_BLK, 256>>>();
    csr_fill_kernel<<<edge_blocks, 256>>>(src, dst);

    pool_kernel<<<dim3(NG, 8), DD>>>(h_in, 0);

    for (int l = 0; l < NL; l++) {
        const float* hcur = (l == 0) ? h_in : hbuf;
        float* st1 = stats + (l * 2 + 0) * 2 * DD;
        float* st2 = stats + (l * 2 + 1) * 2 * DD;

        // z = h + sum_neighbors h  (gather, register accumulate)
        agg_kernel<<<agg_blocks, 256>>>(
            reinterpret_cast<const float4*>(hcur),
            reinterpret_cast<float4*>(zbuf));

        // y = z @ W1 + b1 ; stats1
        gemm_kernel<0><<<gemm_blocks, 128, gemm_smem>>>(
            zbuf, W1 + l * DD * DD, b1 + l * DD, aff, ybuf, st1);
        finalize_kernel<<<1, DD>>>(st1, bn1g + l * DD, bn1b + l * DD);

        // z2 = relu(bn1(y)) @ W2 + b2 ; stats2 ; z2 -> zbuf
        gemm_kernel<1><<<gemm_blocks, 128, gemm_smem>>>(
            ybuf, W2 + l * DD * DD, b2 + l * DD, aff, zbuf, st2);
        finalize_kernel<<<1, DD>>>(st2, bng + l * DD, bnb + l * DD);

        // h = prelu(bn(z2))
        prelu_kernel<<<elt_blocks, 256>>>(prelua);
        pool_kernel<<<dim3(NG, 8), DD>>>(hbuf, l + 1);
    }

    heads_kernel<<<NH, DD, heads_smem>>>(linW, linb, out);
}